// round 13
// baseline (speedup 1.0000x reference)
#include <cuda_runtime.h>
#include <cuda_bf16.h>
#include <cstdint>

#define A_DIM 512
#define C_DIM 345
#define N_DIM 128
#define CPAD  384

#define SW_SCALE 64.0f     // dW -> e4m3 scale
#define SS_SCALE 256.0f    // Sig-> e4m3 scale
#define INV_PSCALE (1.0f / (64.0f * 256.0f))

// ---------------------------------------------------------------------------
// Scratch (device globals; no allocation allowed)
// ---------------------------------------------------------------------------
__device__ __align__(1024) uint32_t g_S8[(size_t)N_DIM * A_DIM * A_DIM / 4];  // e4m3 Sig x256 [slot][a][b] 34MB
__device__ __align__(1024) uint32_t g_dW8[(size_t)N_DIM * CPAD * A_DIM / 4];  // e4m3 dW x64 [slot][c][b] 25MB
__device__ float g_f16[16][N_DIM][CPAD];  // partial f per (a-chunk, k-half)
__device__ float g_nll[N_DIM];
__device__ int   g_slot[N_DIM];
__device__ int   g_first[N_DIM];
__device__ int   g_lbl[N_DIM];

// ---------------------------------------------------------------------------
// Helpers
// ---------------------------------------------------------------------------
__device__ __forceinline__ uint32_t smem_u32(const void* p) {
    uint32_t a;
    asm("{ .reg .u64 t; cvta.to.shared.u64 t, %1; cvt.u32.u64 %0, t; }" : "=r"(a) : "l"(p));
    return a;
}
__device__ __forceinline__ void cp16(uint32_t dst, const void* src) {
    asm volatile("cp.async.cg.shared.global [%0], [%1], 16;" :: "r"(dst), "l"(src));
}
#define CP_COMMIT() asm volatile("cp.async.commit_group;")
#define CP_WAIT(N)  asm volatile("cp.async.wait_group %0;" :: "n"(N))

#define LDSM4(r0, r1, r2, r3, addr)                                            \
    asm volatile("ldmatrix.sync.aligned.m8n8.x4.shared.b16 {%0,%1,%2,%3}, [%4];" \
        : "=r"(r0), "=r"(r1), "=r"(r2), "=r"(r3) : "r"(addr))

#define MMAFP8(d, a, b0, b1)                                                   \
    asm volatile("mma.sync.aligned.m16n8k32.row.col.f32.e4m3.e4m3.f32 "        \
        "{%0,%1,%2,%3},{%4,%5,%6,%7},{%8,%9},{%0,%1,%2,%3};"                   \
        : "+f"((d)[0]), "+f"((d)[1]), "+f"((d)[2]), "+f"((d)[3])               \
        : "r"((a)[0]), "r"((a)[1]), "r"((a)[2]), "r"((a)[3]), "r"(b0), "r"(b1))

// pack 4 floats -> 4 e4m3 bytes (little-endian x,y,z,w)
__device__ __forceinline__ uint32_t pack_e4m3x4(float x, float y, float z, float w) {
    unsigned short lo, hi;
    asm("cvt.rn.satfinite.e4m3x2.f32 %0, %1, %2;" : "=h"(lo) : "f"(y), "f"(x));
    asm("cvt.rn.satfinite.e4m3x2.f32 %0, %1, %2;" : "=h"(hi) : "f"(w), "f"(z));
    return (uint32_t)lo | ((uint32_t)hi << 16);
}

// Label dtype detection (jax may emit int32 or int64)
__device__ __forceinline__ int label_is64(const void* lp) {
    const long long* p = (const long long*)lp;
    int ok = 1;
#pragma unroll 1
    for (int i = 0; i < 64; i++) {
        long long v = p[i];
        if (v < 0 || v >= C_DIM) { ok = 0; break; }
    }
    return ok;
}
__device__ __forceinline__ int get_label(const void* lp, int n, int is64) {
    return is64 ? (int)((const long long*)lp)[n] : ((const int*)lp)[n];
}

// ---------------------------------------------------------------------------
// prep: slot/first/label tables
// ---------------------------------------------------------------------------
__global__ void prep_labels(const void* __restrict__ labels) {
    const int t = threadIdx.x;
    const int is64 = label_is64(labels);
    const int ln = get_label(labels, t, is64);
    int slot = t, first = 1;
    for (int m = 0; m < t; m++)
        if (get_label(labels, m, is64) == ln) { slot = m; first = 0; break; }
    g_slot[t] = slot;
    g_first[t] = first;
    g_lbl[t] = ln;
}

// dW8[slot][c][b] = e4m3((W[c,b]-W[l,b])*64), zero-pad c >= C_DIM
__global__ void conv_dw8(const float* __restrict__ Wg) {
    const int c = blockIdx.x, n = blockIdx.y, t = threadIdx.x;
    if (!g_first[n]) return;
    const int l = g_lbl[n];
    uint32_t packed = 0u;
    if (c < C_DIM) {
        const float4 w  = *(const float4*)(Wg + (size_t)c * A_DIM + 4 * t);
        const float4 wl = *(const float4*)(Wg + (size_t)l * A_DIM + 4 * t);
        packed = pack_e4m3x4((w.x - wl.x) * SW_SCALE, (w.y - wl.y) * SW_SCALE,
                             (w.z - wl.z) * SW_SCALE, (w.w - wl.w) * SW_SCALE);
    }
    g_dW8[((size_t)n * CPAD + c) * (A_DIM / 4) + t] = packed;
}

// cast Sigma_l*256 -> e4m3, row-major; 8 float4 per thread (MLP), coalesced
__global__ __launch_bounds__(256, 8)
void conv_sig(const float* __restrict__ cov) {
    const int n = blockIdx.z;
    if (!g_first[n]) return;
    const int l = g_lbl[n];
    const float4* src = (const float4*)(cov + (size_t)l * A_DIM * A_DIM);
    uint32_t* dst = g_S8 + (size_t)n * (A_DIM * A_DIM / 4);
    const int base = blockIdx.x * 2048 + threadIdx.x;
#pragma unroll
    for (int i = 0; i < 8; i++) {
        const int idx = base + i * 256;
        const float4 v = src[idx];
        dst[idx] = pack_e4m3x4(v.x * SS_SCALE, v.y * SS_SCALE,
                               v.z * SS_SCALE, v.w * SS_SCALE);
    }
}

// ---------------------------------------------------------------------------
// Main fp8 GEMM, tile 128c x 64a x 256k: CTA = (c-tile, a-chunk*2+k-half, slot)
//   Q[c,a] = sum_{b in half} dW8[c,b] * S8[a,b]
//   D = 32 regs/thread; launch_bounds(256,3) -> 3 CTAs/SM (24 warps).
//   All 4 k-chunks (48KB) staged up front; ONE wait + ONE barrier; full unroll.
// ---------------------------------------------------------------------------
#define STG_A   0                       // 4 x 8192 = 32KB
#define STG_B   32768                   // 4 x 4096 = 16KB
#define OFF_WL  49152                   // 512 f32
#define OFF_DM  (OFF_WL + 2048)
#define OFF_Q   (OFF_DM + 2048)         // 128*2 f32
#define OFF_L   (OFF_Q + 1024)
#define SMEM_DYN (OFF_L + 1024)

__global__ __launch_bounds__(256, 3)
void gemm_kernel(const float* __restrict__ Wg,
                 const float* __restrict__ Lam_p,
                 const float* __restrict__ ms,
                 const float* __restrict__ mt) {
    extern __shared__ __align__(128) char dsm[];
    const int n = blockIdx.z;
    if (!g_first[n]) return;
    const int ai = blockIdx.y >> 1;     // a-chunk 0..7 (64-wide)
    const int ki = blockIdx.y & 1;      // k-half  0..1

    const uint32_t sb = smem_u32(dsm);
    float* sWl = (float*)(dsm + OFF_WL);
    float* sDM = (float*)(dsm + OFF_DM);
    float* sQ  = (float*)(dsm + OFF_Q);
    float* sL  = (float*)(dsm + OFF_L);

    const int c0 = blockIdx.x * 128;
    const int t = threadIdx.x;
    const int lane = t & 31, w = t >> 5;
    const int wm = w & 3, wn = w >> 2;  // 4m x 2n warp grid

    const int l = g_lbl[n];

    const char* gA = (const char*)g_dW8 + (size_t)n * CPAD * A_DIM + ki * 256;
    const char* gB = (const char*)g_S8 + ((size_t)n * A_DIM + ai * 64) * A_DIM + ki * 256;

    // stage all 4 chunks of this K-half up front (A 32KB + B 16KB)
    {
        const int m0 = t >> 2, ch0 = t & 3;
        const uint32_t so0 = (uint32_t)(m0 * 64 + ((ch0 ^ ((m0 >> 1) & 3)) << 4));
        const int m1 = (t + 256) >> 2, ch1 = (t + 256) & 3;
        const uint32_t so1 = (uint32_t)(m1 * 64 + ((ch1 ^ ((m1 >> 1) & 3)) << 4));
#pragma unroll
        for (int ck = 0; ck < 4; ck++) {
            const int b0 = ck * 64;
            cp16(sb + STG_A + ck * 8192 + so0, gA + (size_t)(c0 + m0) * A_DIM + b0 + ch0 * 16);
            cp16(sb + STG_A + ck * 8192 + so1, gA + (size_t)(c0 + m1) * A_DIM + b0 + ch1 * 16);
            cp16(sb + STG_B + ck * 4096 + so0, gB + (size_t)m0 * A_DIM + b0 + ch0 * 16);
        }
        CP_COMMIT();
    }

    // independent: stage Wl / dM while cp.async flies
    for (int a = t; a < A_DIM; a += 256) {
        sWl[a] = Wg[(size_t)l * A_DIM + a];
        sDM[a] = mt[(size_t)l * A_DIM + a] - ms[(size_t)l * A_DIM + a];
    }

    // per-lane ldmatrix geometry
    const int lj = lane >> 3, li = lane & 7;
    const int amr0 = wm * 32 + (lj & 1) * 8 + li;
    const int amr1 = amr0 + 16;
    const int akc  = lj >> 1;
    const int asw0 = (amr0 >> 1) & 3, asw1 = (amr1 >> 1) & 3;
    int bnr[2], bsw[2];
#pragma unroll
    for (int np = 0; np < 2; np++) {
        bnr[np] = wn * 32 + np * 16 + (lj >> 1) * 8 + li;
        bsw[np] = (bnr[np] >> 1) & 3;
    }
    const int bkc = lj & 1;

    float D[2][4][4];
#pragma unroll
    for (int mi = 0; mi < 2; mi++)
#pragma unroll
        for (int ni = 0; ni < 4; ni++)
#pragma unroll
            for (int e = 0; e < 4; e++) D[mi][ni][e] = 0.f;

    CP_WAIT(0);
    __syncthreads();            // the ONLY mainloop barrier

#pragma unroll
    for (int k = 0; k < 4; k++) {
        const uint32_t Ab = sb + STG_A + k * 8192;
        const uint32_t Bb = sb + STG_B + k * 4096;
#pragma unroll
        for (int s = 0; s < 2; s++) {
            uint32_t a0r[4], a1r[4], br[2][4];
            LDSM4(a0r[0], a0r[1], a0r[2], a0r[3],
                  Ab + amr0 * 64 + (((2 * s + akc) ^ asw0) << 4));
            LDSM4(a1r[0], a1r[1], a1r[2], a1r[3],
                  Ab + amr1 * 64 + (((2 * s + akc) ^ asw1) << 4));
#pragma unroll
            for (int np = 0; np < 2; np++)
                LDSM4(br[np][0], br[np][1], br[np][2], br[np][3],
                      Bb + bnr[np] * 64 + (((2 * s + bkc) ^ bsw[np]) << 4));
#pragma unroll
            for (int ni = 0; ni < 4; ni++) {
                const uint32_t b0 = br[ni >> 1][(ni & 1) * 2];
                const uint32_t b1 = br[ni >> 1][(ni & 1) * 2 + 1];
                MMAFP8(D[0][ni], a0r, b0, b1);
                MMAFP8(D[1][ni], a1r, b0, b1);
            }
        }
    }

    // epilogue: contract Q-frags against fp32 dw; lin only on ki==0
    float qacc[4] = {0, 0, 0, 0}, lacc[4] = {0, 0, 0, 0};
#pragma unroll
    for (int mi = 0; mi < 2; mi++) {
        const int crb = c0 + wm * 32 + mi * 16 + (lane >> 2);
#pragma unroll
        for (int half = 0; half < 2; half++) {
            const int cr = crb + half * 8;
            if (cr < C_DIM) {
                const float* wrow = Wg + (size_t)cr * A_DIM;
                float q = 0.f, li2 = 0.f;
#pragma unroll
                for (int ni = 0; ni < 4; ni++) {
                    const int al = wn * 32 + ni * 8 + (lane & 3) * 2;
                    const int a  = ai * 64 + al;
                    const float2 wv = *(const float2*)(wrow + a);
                    const float dw0 = wv.x - sWl[a], dw1 = wv.y - sWl[a + 1];
                    q += D[mi][ni][half * 2 + 0] * dw0
                       + D[mi][ni][half * 2 + 1] * dw1;
                    li2 += dw0 * sDM[a] + dw1 * sDM[a + 1];
                }
                qacc[mi * 2 + half] += q;
                lacc[mi * 2 + half] += li2;
            }
        }
    }

#pragma unroll
    for (int i = 0; i < 4; i++) {
        qacc[i] += __shfl_xor_sync(~0u, qacc[i], 1);
        qacc[i] += __shfl_xor_sync(~0u, qacc[i], 2);
        lacc[i] += __shfl_xor_sync(~0u, lacc[i], 1);
        lacc[i] += __shfl_xor_sync(~0u, lacc[i], 2);
    }
    if ((lane & 3) == 0) {
#pragma unroll
        for (int i = 0; i < 4; i++) {
            const int row = wm * 32 + (i >> 1) * 16 + (i & 1) * 8 + (lane >> 2);
            sQ[row * 2 + wn] = qacc[i];
            sL[row * 2 + wn] = lacc[i];
        }
    }
    __syncthreads();
    if (t < 128) {
        const int c = c0 + t;
        if (c < C_DIM) {
            const float Lam = Lam_p[0];
            const float q = (sQ[t * 2] + sQ[t * 2 + 1]) * INV_PSCALE;
            const float li2 = (ki == 0) ? (sL[t * 2] + sL[t * 2 + 1]) : 0.f;
            g_f16[ai * 2 + ki][n][c] = 0.5f * Lam * q + Lam * li2;
        }
    }
}

// ---------------------------------------------------------------------------
// NLL + mean
// ---------------------------------------------------------------------------
__device__ __forceinline__ float fsum16(int sl, int c) {
    float s = 0.f;
#pragma unroll
    for (int i = 0; i < 16; i++) s += g_f16[i][sl][c];
    return s;
}

__global__ void nll_kernel(const float* __restrict__ ys) {
    __shared__ float sm[128];
    const int n = blockIdx.x, t = threadIdx.x;
    const int sl = g_slot[n];
    const float v0 = ys[(size_t)n * C_DIM + t] + fsum16(sl, t);
    const float v1 = ys[(size_t)n * C_DIM + t + 128] + fsum16(sl, t + 128);
    const float v2 = (t + 256 < C_DIM)
                   ? ys[(size_t)n * C_DIM + t + 256] + fsum16(sl, t + 256) : -1e30f;
    float mx = fmaxf(v0, fmaxf(v1, v2));
    sm[t] = mx; __syncthreads();
    for (int s = 64; s > 0; s >>= 1) { if (t < s) sm[t] = fmaxf(sm[t], sm[t + s]); __syncthreads(); }
    const float MX = sm[0]; __syncthreads();
    float e = expf(v0 - MX) + expf(v1 - MX);
    if (t + 256 < C_DIM) e += expf(v2 - MX);
    sm[t] = e; __syncthreads();
    for (int s = 64; s > 0; s >>= 1) { if (t < s) sm[t] += sm[t + s]; __syncthreads(); }
    if (t == 0) {
        const int lb = g_lbl[n];
        const float pick = ys[(size_t)n * C_DIM + lb] + fsum16(sl, lb);
        g_nll[n] = logf(sm[0]) + MX - pick;
    }
}

__global__ void mean_kernel(float* __restrict__ out) {
    __shared__ float sm[128];
    const int t = threadIdx.x;
    sm[t] = g_nll[t]; __syncthreads();
    for (int s = 64; s > 0; s >>= 1) { if (t < s) sm[t] += sm[t + s]; __syncthreads(); }
    if (t == 0) out[0] = sm[0] * (1.0f / (float)N_DIM);
}

// ---------------------------------------------------------------------------
// Host launcher
// ---------------------------------------------------------------------------
extern "C" void kernel_launch(void* const* d_in, const int* in_sizes, int n_in,
                              void* d_out, int out_size) {
    const float* W      = (const float*)d_in[0];
    const float* ys     = (const float*)d_in[2];
    const void*  labels = d_in[3];
    const float* Lam    = (const float*)d_in[4];
    const float* ms     = (const float*)d_in[5];
    const float* mt     = (const float*)d_in[6];
    const float* cov    = (const float*)d_in[7];
    float* out = (float*)d_out;

    static int attr_set = 0;
    if (!attr_set) {
        cudaFuncSetAttribute(gemm_kernel, cudaFuncAttributeMaxDynamicSharedMemorySize,
                             SMEM_DYN);
        attr_set = 1;
    }

    prep_labels<<<1, N_DIM>>>(labels);
    conv_dw8<<<dim3(CPAD, N_DIM), 128>>>(W);
    conv_sig<<<dim3(32, 1, N_DIM), 256>>>(cov);
    gemm_kernel<<<dim3(3, 16, N_DIM), 256, SMEM_DYN>>>(W, Lam, ms, mt);
    nll_kernel<<<N_DIM, 128>>>(ys);
    mean_kernel<<<1, 128>>>(out);
}

// round 15
// speedup vs baseline: 1.1829x; 1.1829x over previous
#include <cuda_runtime.h>
#include <cuda_bf16.h>
#include <cstdint>

#define A_DIM 512
#define C_DIM 345
#define N_DIM 128
#define CPAD  384

#define SW_SCALE 64.0f     // dW -> e4m3 scale
#define SS_SCALE 256.0f    // Sig-> e4m3 scale
#define INV_PSCALE (1.0f / (64.0f * 256.0f))

// ---------------------------------------------------------------------------
// Scratch (device globals; no allocation allowed)
// ---------------------------------------------------------------------------
__device__ __align__(1024) uint32_t g_S8[(size_t)N_DIM * A_DIM * A_DIM / 4];  // e4m3 Sig x256 [slot][a][b] 34MB
__device__ __align__(1024) uint32_t g_dW8[(size_t)N_DIM * CPAD * A_DIM / 4];  // e4m3 dW x64 [slot][c][b] 25MB
__device__ float g_f4[4][N_DIM][CPAD];    // partial f per a-chunk
__device__ float g_nll[N_DIM];
__device__ int   g_slot[N_DIM];
__device__ int   g_first[N_DIM];
__device__ int   g_lbl[N_DIM];

// ---------------------------------------------------------------------------
// Helpers
// ---------------------------------------------------------------------------
__device__ __forceinline__ uint32_t smem_u32(const void* p) {
    uint32_t a;
    asm("{ .reg .u64 t; cvta.to.shared.u64 t, %1; cvt.u32.u64 %0, t; }" : "=r"(a) : "l"(p));
    return a;
}
__device__ __forceinline__ void cp16(uint32_t dst, const void* src) {
    asm volatile("cp.async.cg.shared.global [%0], [%1], 16;" :: "r"(dst), "l"(src));
}
#define CP_COMMIT() asm volatile("cp.async.commit_group;")
#define CP_WAIT(N)  asm volatile("cp.async.wait_group %0;" :: "n"(N))

#define LDSM4(r0, r1, r2, r3, addr)                                            \
    asm volatile("ldmatrix.sync.aligned.m8n8.x4.shared.b16 {%0,%1,%2,%3}, [%4];" \
        : "=r"(r0), "=r"(r1), "=r"(r2), "=r"(r3) : "r"(addr))

#define MMAFP8(d, a, b0, b1)                                                   \
    asm volatile("mma.sync.aligned.m16n8k32.row.col.f32.e4m3.e4m3.f32 "        \
        "{%0,%1,%2,%3},{%4,%5,%6,%7},{%8,%9},{%0,%1,%2,%3};"                   \
        : "+f"((d)[0]), "+f"((d)[1]), "+f"((d)[2]), "+f"((d)[3])               \
        : "r"((a)[0]), "r"((a)[1]), "r"((a)[2]), "r"((a)[3]), "r"(b0), "r"(b1))

// pack 4 floats -> 4 e4m3 bytes (little-endian x,y,z,w)
__device__ __forceinline__ uint32_t pack_e4m3x4(float x, float y, float z, float w) {
    unsigned short lo, hi;
    asm("cvt.rn.satfinite.e4m3x2.f32 %0, %1, %2;" : "=h"(lo) : "f"(y), "f"(x));
    asm("cvt.rn.satfinite.e4m3x2.f32 %0, %1, %2;" : "=h"(hi) : "f"(w), "f"(z));
    return (uint32_t)lo | ((uint32_t)hi << 16);
}

// Label dtype detection (jax may emit int32 or int64)
__device__ __forceinline__ int label_is64(const void* lp) {
    const long long* p = (const long long*)lp;
    int ok = 1;
#pragma unroll 1
    for (int i = 0; i < 64; i++) {
        long long v = p[i];
        if (v < 0 || v >= C_DIM) { ok = 0; break; }
    }
    return ok;
}
__device__ __forceinline__ int get_label(const void* lp, int n, int is64) {
    return is64 ? (int)((const long long*)lp)[n] : ((const int*)lp)[n];
}

// ---------------------------------------------------------------------------
// prep: slot/first/label tables
// ---------------------------------------------------------------------------
__global__ void prep_labels(const void* __restrict__ labels) {
    const int t = threadIdx.x;
    const int is64 = label_is64(labels);
    const int ln = get_label(labels, t, is64);
    int slot = t, first = 1;
    for (int m = 0; m < t; m++)
        if (get_label(labels, m, is64) == ln) { slot = m; first = 0; break; }
    g_slot[t] = slot;
    g_first[t] = first;
    g_lbl[t] = ln;
}

// ---------------------------------------------------------------------------
// conv_dw8 v2: dW8[slot][c][b] = e4m3((W[c,b]-W[l,b])*64), zero-pad c>=C_DIM.
// Block = (48-c band, slot). Wl staged once; W rows streamed via LDG.128;
// coalesced STG.32 (512B/row-half). ~100MB L2 traffic total.
// ---------------------------------------------------------------------------
__global__ __launch_bounds__(256, 8)
void conv_dw8(const float* __restrict__ Wg) {
    const int n = blockIdx.y;
    if (!g_first[n]) return;
    const int l = g_lbl[n];
    __shared__ float sWl[A_DIM];
    const int t = threadIdx.x;
    for (int a = t; a < A_DIM; a += 256) sWl[a] = Wg[(size_t)l * A_DIM + a];
    __syncthreads();

    const int cbase = blockIdx.x * 48;
    const int cl  = t >> 7;          // 0/1: which of 2 rows this iter
    const int col = t & 127;         // uint32 (4-elem) column
#pragma unroll 1
    for (int cb = 0; cb < 48; cb += 2) {
        const int c = cbase + cb + cl;
        uint32_t packed = 0u;
        if (c < C_DIM) {
            const float4 w = *(const float4*)(Wg + (size_t)c * A_DIM + col * 4);
            packed = pack_e4m3x4((w.x - sWl[col * 4 + 0]) * SW_SCALE,
                                 (w.y - sWl[col * 4 + 1]) * SW_SCALE,
                                 (w.z - sWl[col * 4 + 2]) * SW_SCALE,
                                 (w.w - sWl[col * 4 + 3]) * SW_SCALE);
        }
        g_dW8[((size_t)n * CPAD + c) * (A_DIM / 4) + col] = packed;
    }
}

// cast Sigma_l*256 -> e4m3, row-major; 8 float4 per thread (MLP), coalesced
__global__ __launch_bounds__(256, 8)
void conv_sig(const float* __restrict__ cov) {
    const int n = blockIdx.z;
    if (!g_first[n]) return;
    const int l = g_lbl[n];
    const float4* src = (const float4*)(cov + (size_t)l * A_DIM * A_DIM);
    uint32_t* dst = g_S8 + (size_t)n * (A_DIM * A_DIM / 4);
    const int base = blockIdx.x * 2048 + threadIdx.x;
#pragma unroll
    for (int i = 0; i < 8; i++) {
        const int idx = base + i * 256;
        const float4 v = src[idx];
        dst[idx] = pack_e4m3x4(v.x * SS_SCALE, v.y * SS_SCALE,
                               v.z * SS_SCALE, v.w * SS_SCALE);
    }
}

// ---------------------------------------------------------------------------
// Main fp8 GEMM (R11 config — best measured): CTA = (c-tile, a-chunk, slot).
//   Q[c,a] = sum_b dW8[c,b] * S8[a,b]   (m=c, n=a, k=b; both row-major)
//   quad[c]+= sum_a Q[c,a] * dw[c,a] / 16384   (dw fp32 in epilogue)
//   lin[c] += sum_a dw[c,a] * dM[a]
// 4-stage cp.async pipeline, ONE __syncthreads per k-iter.
// ---------------------------------------------------------------------------
#define STG_A   0                       // 4 x 8192
#define STG_B   32768                   // 4 x 8192
#define OFF_WL  65536                   // 512 f32
#define OFF_DM  (OFF_WL + 2048)
#define OFF_Q   (OFF_DM + 2048)         // 128*2 f32
#define OFF_L   (OFF_Q + 1024)
#define SMEM_DYN (OFF_L + 1024)

__global__ __launch_bounds__(256, 2)
void gemm_kernel(const float* __restrict__ Wg,
                 const float* __restrict__ Lam_p,
                 const float* __restrict__ ms,
                 const float* __restrict__ mt) {
    extern __shared__ __align__(128) char dsm[];
    const int n = blockIdx.z;
    if (!g_first[n]) return;
    const int ai = blockIdx.y;

    const uint32_t sb = smem_u32(dsm);
    float* sWl = (float*)(dsm + OFF_WL);
    float* sDM = (float*)(dsm + OFF_DM);
    float* sQ  = (float*)(dsm + OFF_Q);
    float* sL  = (float*)(dsm + OFF_L);

    const int c0 = blockIdx.x * 128;
    const int t = threadIdx.x;
    const int lane = t & 31, w = t >> 5;
    const int wm = w & 3, wn = w >> 2;

    const int l = g_lbl[n];

    const char* gA = (const char*)g_dW8 + (size_t)n * CPAD * A_DIM;
    const char* gB = (const char*)g_S8 + ((size_t)n * A_DIM + ai * 128) * A_DIM;

    auto stage = [&](int st, int ck) {
        const int b0 = ck * 64;   // byte == elem offset along k(b)
#pragma unroll
        for (int p = 0; p < 2; p++) {
            const int id = t + 256 * p;
            const int m = id >> 2, ch = id & 3;
            const uint32_t so = (uint32_t)(m * 64 + ((ch ^ ((m >> 1) & 3)) << 4));
            cp16(sb + STG_A + st * 8192 + so, gA + (size_t)(c0 + m) * A_DIM + b0 + ch * 16);
            cp16(sb + STG_B + st * 8192 + so, gB + (size_t)m * A_DIM + b0 + ch * 16);
        }
        CP_COMMIT();
    };

    stage(0, 0); stage(1, 1); stage(2, 2);

    // independent: stage Wl / dM while cp.async flies
    for (int a = t; a < A_DIM; a += 256) {
        sWl[a] = Wg[(size_t)l * A_DIM + a];
        sDM[a] = mt[(size_t)l * A_DIM + a] - ms[(size_t)l * A_DIM + a];
    }

    // per-lane ldmatrix geometry
    const int lj = lane >> 3, li = lane & 7;
    const int amr0 = wm * 32 + (lj & 1) * 8 + li;
    const int amr1 = amr0 + 16;
    const int akc  = lj >> 1;
    const int asw0 = (amr0 >> 1) & 3, asw1 = (amr1 >> 1) & 3;
    int bnr[4], bsw[4];
#pragma unroll
    for (int np = 0; np < 4; np++) {
        bnr[np] = wn * 64 + np * 16 + (lj >> 1) * 8 + li;
        bsw[np] = (bnr[np] >> 1) & 3;
    }
    const int bkc = lj & 1;

    float D[2][8][4];
#pragma unroll
    for (int mi = 0; mi < 2; mi++)
#pragma unroll
        for (int ni = 0; ni < 8; ni++)
#pragma unroll
            for (int e = 0; e < 4; e++) D[mi][ni][e] = 0.f;

#pragma unroll 1
    for (int k = 0; k < 8; k++) {
        if (k < 6) CP_WAIT(2);
        else if (k == 6) CP_WAIT(1);
        else CP_WAIT(0);
        __syncthreads();

        const int st = k & 3;
        const uint32_t Ab = sb + STG_A + st * 8192;
        const uint32_t Bb = sb + STG_B + st * 8192;
#pragma unroll
        for (int s = 0; s < 2; s++) {
            uint32_t a0r[4], a1r[4], br[4][4];
            LDSM4(a0r[0], a0r[1], a0r[2], a0r[3],
                  Ab + amr0 * 64 + (((2 * s + akc) ^ asw0) << 4));
            LDSM4(a1r[0], a1r[1], a1r[2], a1r[3],
                  Ab + amr1 * 64 + (((2 * s + akc) ^ asw1) << 4));
#pragma unroll
            for (int np = 0; np < 4; np++)
                LDSM4(br[np][0], br[np][1], br[np][2], br[np][3],
                      Bb + bnr[np] * 64 + (((2 * s + bkc) ^ bsw[np]) << 4));
#pragma unroll
            for (int ni = 0; ni < 8; ni++) {
                const uint32_t b0 = br[ni >> 1][(ni & 1) * 2];
                const uint32_t b1 = br[ni >> 1][(ni & 1) * 2 + 1];
                MMAFP8(D[0][ni], a0r, b0, b1);
                MMAFP8(D[1][ni], a1r, b0, b1);
            }
        }
        // stage into (k+3)&3 == (k-1)&3: consumed last iter, all warps past
        // this iter's barrier -> WAR-safe with a single sync per iteration.
        if (k + 3 < 8) stage((k + 3) & 3, k + 3);
    }

    // epilogue: contract Q-frags against fp32 dw and dM
    float qacc[4] = {0, 0, 0, 0}, lacc[4] = {0, 0, 0, 0};
#pragma unroll
    for (int mi = 0; mi < 2; mi++) {
        const int crb = c0 + wm * 32 + mi * 16 + (lane >> 2);
#pragma unroll
        for (int half = 0; half < 2; half++) {
            const int cr = crb + half * 8;
            if (cr < C_DIM) {
                const float* wrow = Wg + (size_t)cr * A_DIM;
                float q = 0.f, li2 = 0.f;
#pragma unroll
                for (int ni = 0; ni < 8; ni++) {
                    const int al = wn * 64 + ni * 8 + (lane & 3) * 2;
                    const int a  = ai * 128 + al;
                    const float2 wv = *(const float2*)(wrow + a);
                    const float dw0 = wv.x - sWl[a], dw1 = wv.y - sWl[a + 1];
                    q += D[mi][ni][half * 2 + 0] * dw0
                       + D[mi][ni][half * 2 + 1] * dw1;
                    li2 += dw0 * sDM[a] + dw1 * sDM[a + 1];
                }
                qacc[mi * 2 + half] += q;
                lacc[mi * 2 + half] += li2;
            }
        }
    }

#pragma unroll
    for (int i = 0; i < 4; i++) {
        qacc[i] += __shfl_xor_sync(~0u, qacc[i], 1);
        qacc[i] += __shfl_xor_sync(~0u, qacc[i], 2);
        lacc[i] += __shfl_xor_sync(~0u, lacc[i], 1);
        lacc[i] += __shfl_xor_sync(~0u, lacc[i], 2);
    }
    if ((lane & 3) == 0) {
#pragma unroll
        for (int i = 0; i < 4; i++) {
            const int row = wm * 32 + (i >> 1) * 16 + (i & 1) * 8 + (lane >> 2);
            sQ[row * 2 + wn] = qacc[i];
            sL[row * 2 + wn] = lacc[i];
        }
    }
    __syncthreads();
    if (t < 128) {
        const int c = c0 + t;
        if (c < C_DIM) {
            const float Lam = Lam_p[0];
            const float q = (sQ[t * 2] + sQ[t * 2 + 1]) * INV_PSCALE;
            const float li2 = sL[t * 2] + sL[t * 2 + 1];
            g_f4[ai][n][c] = 0.5f * Lam * q + Lam * li2;
        }
    }
}

// ---------------------------------------------------------------------------
// NLL + mean
// ---------------------------------------------------------------------------
__global__ void nll_kernel(const float* __restrict__ ys) {
    __shared__ float sm[128];
    const int n = blockIdx.x, t = threadIdx.x;
    const int sl = g_slot[n];
#define FSUM(c) (g_f4[0][sl][c] + g_f4[1][sl][c] + g_f4[2][sl][c] + g_f4[3][sl][c])
    const float v0 = ys[(size_t)n * C_DIM + t] + FSUM(t);
    const float v1 = ys[(size_t)n * C_DIM + t + 128] + FSUM(t + 128);
    const float v2 = (t + 256 < C_DIM)
                   ? ys[(size_t)n * C_DIM + t + 256] + FSUM(t + 256) : -1e30f;
    float mx = fmaxf(v0, fmaxf(v1, v2));
    sm[t] = mx; __syncthreads();
    for (int s = 64; s > 0; s >>= 1) { if (t < s) sm[t] = fmaxf(sm[t], sm[t + s]); __syncthreads(); }
    const float MX = sm[0]; __syncthreads();
    float e = expf(v0 - MX) + expf(v1 - MX);
    if (t + 256 < C_DIM) e += expf(v2 - MX);
    sm[t] = e; __syncthreads();
    for (int s = 64; s > 0; s >>= 1) { if (t < s) sm[t] += sm[t + s]; __syncthreads(); }
    if (t == 0) {
        const int lb = g_lbl[n];
        const float pick = ys[(size_t)n * C_DIM + lb] + FSUM(lb);
        g_nll[n] = logf(sm[0]) + MX - pick;
    }
#undef FSUM
}

__global__ void mean_kernel(float* __restrict__ out) {
    __shared__ float sm[128];
    const int t = threadIdx.x;
    sm[t] = g_nll[t]; __syncthreads();
    for (int s = 64; s > 0; s >>= 1) { if (t < s) sm[t] += sm[t + s]; __syncthreads(); }
    if (t == 0) out[0] = sm[0] * (1.0f / (float)N_DIM);
}

// ---------------------------------------------------------------------------
// Host launcher
// ---------------------------------------------------------------------------
extern "C" void kernel_launch(void* const* d_in, const int* in_sizes, int n_in,
                              void* d_out, int out_size) {
    const float* W      = (const float*)d_in[0];
    const float* ys     = (const float*)d_in[2];
    const void*  labels = d_in[3];
    const float* Lam    = (const float*)d_in[4];
    const float* ms     = (const float*)d_in[5];
    const float* mt     = (const float*)d_in[6];
    const float* cov    = (const float*)d_in[7];
    float* out = (float*)d_out;

    static int attr_set = 0;
    if (!attr_set) {
        cudaFuncSetAttribute(gemm_kernel, cudaFuncAttributeMaxDynamicSharedMemorySize,
                             SMEM_DYN);
        attr_set = 1;
    }

    prep_labels<<<1, N_DIM>>>(labels);
    conv_dw8<<<dim3(8, N_DIM), 256>>>(W);
    conv_sig<<<dim3(32, 1, N_DIM), 256>>>(cov);
    gemm_kernel<<<dim3(3, 4, N_DIM), 256, SMEM_DYN>>>(W, Lam, ms, mt);
    nll_kernel<<<N_DIM, 128>>>(ys);
    mean_kernel<<<1, 128>>>(out);
}